// round 2
// baseline (speedup 1.0000x reference)
#include <cuda_runtime.h>
#include <math.h>

#define BB 4
#define NN 2048
#define DD 512
#define HH 8
#define EE 2048            // 2*64*8 + 2*64*8
#define TOK (BB*NN)        // 8192

// ---------------- scratch (device globals; no allocation allowed) ----------
__device__ float g_normed[TOK*DD];   // 16.8 MB
__device__ float g_proj  [TOK*EE];   // 67 MB  (u|v|q|k)
__device__ float g_attn  [TOK*DD];   // 16.8 MB
__device__ float g_oin   [TOK*DD];   // 16.8 MB

// ---------------- LayerNorm (no affine), row = 512 floats ------------------
__global__ __launch_bounds__(128) void ln_kernel(const float* __restrict__ x,
                                                 float* __restrict__ out)
{
    __shared__ float sh1[4], sh2[4];
    int row = blockIdx.x;
    int t = threadIdx.x;                   // 128 threads, 4 floats each
    float4 a = ((const float4*)(x + (size_t)row*DD))[t];
    float s  = a.x + a.y + a.z + a.w;
    float ss = a.x*a.x + a.y*a.y + a.z*a.z + a.w*a.w;
    #pragma unroll
    for (int o = 16; o > 0; o >>= 1) {
        s  += __shfl_down_sync(0xffffffffu, s,  o);
        ss += __shfl_down_sync(0xffffffffu, ss, o);
    }
    int w = t >> 5, l = t & 31;
    if (l == 0) { sh1[w] = s; sh2[w] = ss; }
    __syncthreads();
    s  = sh1[0] + sh1[1] + sh1[2] + sh1[3];
    ss = sh2[0] + sh2[1] + sh2[2] + sh2[3];
    float mu  = s * (1.0f/DD);
    float var = ss * (1.0f/DD) - mu*mu;
    float inv = rsqrtf(var + 1e-6f);
    float4 o4;
    o4.x = (a.x - mu) * inv; o4.y = (a.y - mu) * inv;
    o4.z = (a.z - mu) * inv; o4.w = (a.w - mu) * inv;
    ((float4*)(out + (size_t)row*DD))[t] = o4;
}

// ---------------- LayerNorm(attn) * u  →  o_input --------------------------
__global__ __launch_bounds__(128) void ln_mul_kernel(const float* __restrict__ attn,
                                                     const float* __restrict__ proj,
                                                     float* __restrict__ out)
{
    __shared__ float sh1[4], sh2[4];
    int row = blockIdx.x;
    int t = threadIdx.x;
    float4 a = ((const float4*)(attn + (size_t)row*DD))[t];
    float s  = a.x + a.y + a.z + a.w;
    float ss = a.x*a.x + a.y*a.y + a.z*a.z + a.w*a.w;
    #pragma unroll
    for (int o = 16; o > 0; o >>= 1) {
        s  += __shfl_down_sync(0xffffffffu, s,  o);
        ss += __shfl_down_sync(0xffffffffu, ss, o);
    }
    int w = t >> 5, l = t & 31;
    if (l == 0) { sh1[w] = s; sh2[w] = ss; }
    __syncthreads();
    s  = sh1[0] + sh1[1] + sh1[2] + sh1[3];
    ss = sh2[0] + sh2[1] + sh2[2] + sh2[3];
    float mu  = s * (1.0f/DD);
    float var = ss * (1.0f/DD) - mu*mu;
    float inv = rsqrtf(var + 1e-6f);
    // u = proj[row, 0:512]
    float4 u = ((const float4*)(proj + (size_t)row*EE))[t];
    float4 o4;
    o4.x = u.x * (a.x - mu) * inv; o4.y = u.y * (a.y - mu) * inv;
    o4.z = u.z * (a.z - mu) * inv; o4.w = u.w * (a.w - mu) * inv;
    ((float4*)(out + (size_t)row*DD))[t] = o4;
}

// ---------------- 128x128x16 register-tiled fp32 GEMM ----------------------
// MODE 0: C = silu(A @ B),               B row-major [K x N]
// MODE 1: C = A @ B^T + bias + resid,    B row-major [N x K] (torch Linear w)
template<int MODE>
__global__ __launch_bounds__(256, 2) void gemm128(
    const float* __restrict__ A, const float* __restrict__ B,
    float* __restrict__ C, int M, int N, int K,
    const float* __restrict__ bias, const float* __restrict__ resid)
{
    __shared__ float As[16][132];   // k-major, stride 132 = 4*33 (aligned float4, 2-way)
    __shared__ float Bs[16][132];
    int tid = threadIdx.x;
    int tx = tid & 15, ty = tid >> 4;
    int m0 = blockIdx.y * 128, n0 = blockIdx.x * 128;
    int r0 = ty * 8, c0 = tx * 8;
    float acc[8][8] = {};

    for (int k0 = 0; k0 < K; k0 += 16) {
        #pragma unroll
        for (int i = 0; i < 2; i++) {
            int idx = tid + i * 256;
            int r  = idx >> 2;
            int kk = (idx & 3) * 4;
            float4 a = *(const float4*)(A + (size_t)(m0 + r) * K + k0 + kk);
            As[kk+0][r] = a.x; As[kk+1][r] = a.y; As[kk+2][r] = a.z; As[kk+3][r] = a.w;
        }
        if (MODE == 0) {
            #pragma unroll
            for (int i = 0; i < 2; i++) {
                int idx = tid + i * 256;
                int r  = idx >> 5;
                int cc = (idx & 31) * 4;
                *(float4*)&Bs[r][cc] = *(const float4*)(B + (size_t)(k0 + r) * N + n0 + cc);
            }
        } else {
            #pragma unroll
            for (int i = 0; i < 2; i++) {
                int idx = tid + i * 256;
                int n  = idx >> 2;
                int kk = (idx & 3) * 4;
                float4 wv = *(const float4*)(B + (size_t)(n0 + n) * K + k0 + kk);
                Bs[kk+0][n] = wv.x; Bs[kk+1][n] = wv.y; Bs[kk+2][n] = wv.z; Bs[kk+3][n] = wv.w;
            }
        }
        __syncthreads();
        #pragma unroll
        for (int k = 0; k < 16; k++) {
            float4 a0 = *(const float4*)&As[k][r0];
            float4 a1 = *(const float4*)&As[k][r0 + 4];
            float4 b0 = *(const float4*)&Bs[k][c0];
            float4 b1 = *(const float4*)&Bs[k][c0 + 4];
            float ra[8] = {a0.x,a0.y,a0.z,a0.w,a1.x,a1.y,a1.z,a1.w};
            float rb[8] = {b0.x,b0.y,b0.z,b0.w,b1.x,b1.y,b1.z,b1.w};
            #pragma unroll
            for (int i = 0; i < 8; i++)
                #pragma unroll
                for (int j = 0; j < 8; j++)
                    acc[i][j] = fmaf(ra[i], rb[j], acc[i][j]);
        }
        __syncthreads();
    }

    #pragma unroll
    for (int i = 0; i < 8; i++) {
        size_t row = (size_t)(m0 + r0 + i);
        float o[8];
        #pragma unroll
        for (int j = 0; j < 8; j++) {
            float v = acc[i][j];
            if (MODE == 0) {
                o[j] = v / (1.0f + expf(-v));          // silu
            } else {
                int col = n0 + c0 + j;
                o[j] = v + bias[col] + resid[row * N + col];
            }
        }
        float* cp = C + row * N + n0 + c0;
        *(float4*)(cp)     = make_float4(o[0], o[1], o[2], o[3]);
        *(float4*)(cp + 4) = make_float4(o[4], o[5], o[6], o[7]);
    }
}

// ---------------- fused causal HSTU attention -------------------------------
// grid = (N/64 row-tiles, B*H). block = 256 (16x16, 4x4 micro-tile).
// All SMEM tiles row-major, stride 68 floats (16B-aligned float4, 2-way max).
#define ASTRIDE 68
#define ATTN_SMEM (4 * 64 * ASTRIDE * (int)sizeof(float))

__global__ __launch_bounds__(256) void attn_kernel(const float* __restrict__ proj,
                                                   float* __restrict__ attn)
{
    extern __shared__ float sm[];
    float* Qs = sm;                       // [64 r][68]  d contiguous
    float* Ks = Qs + 64 * ASTRIDE;        // [64 c][68]
    float* Vs = Ks + 64 * ASTRIDE;        // [64 m][68]
    float* Ss = Vs + 64 * ASTRIDE;        // [64 r][68]  m contiguous

    int tid = threadIdx.x;
    int tx = tid & 15, ty = tid >> 4;
    int rt = blockIdx.x;
    int bh = blockIdx.y;
    int b = bh >> 3, h = bh & 7;
    int row0 = rt * 64;
    const size_t base = (size_t)b * NN * EE;
    const int hc = h * 64;

    #pragma unroll
    for (int i = 0; i < 4; i++) {
        int idx = tid + i * 256;
        int r = idx >> 4;
        int d = (idx & 15) * 4;
        float4 q = *(const float4*)(proj + base + (size_t)(row0 + r) * EE + 1024 + hc + d);
        *(float4*)&Qs[r * ASTRIDE + d] = q;
    }

    float o[4][4] = {};
    int r0 = ty * 4, c0 = tx * 4;
    const float invN = 1.0f / (float)NN;

    for (int mt = 0; mt <= rt; mt++) {
        int m0 = mt * 64;
        #pragma unroll
        for (int i = 0; i < 4; i++) {
            int idx = tid + i * 256;
            int r = idx >> 4;
            int d = (idx & 15) * 4;
            float4 kv = *(const float4*)(proj + base + (size_t)(m0 + r) * EE + 1536 + hc + d);
            *(float4*)&Ks[r * ASTRIDE + d] = kv;
            float4 vv = *(const float4*)(proj + base + (size_t)(m0 + r) * EE + 512 + hc + d);
            *(float4*)&Vs[r * ASTRIDE + d] = vv;
        }
        __syncthreads();

        float s[4][4] = {};
        #pragma unroll
        for (int d = 0; d < 64; d += 4) {
            float4 qa[4], kb[4];
            #pragma unroll
            for (int i = 0; i < 4; i++) qa[i] = *(const float4*)&Qs[(r0 + i) * ASTRIDE + d];
            #pragma unroll
            for (int j = 0; j < 4; j++) kb[j] = *(const float4*)&Ks[(c0 + j) * ASTRIDE + d];
            #pragma unroll
            for (int i = 0; i < 4; i++)
                #pragma unroll
                for (int j = 0; j < 4; j++) {
                    s[i][j] = fmaf(qa[i].x, kb[j].x, s[i][j]);
                    s[i][j] = fmaf(qa[i].y, kb[j].y, s[i][j]);
                    s[i][j] = fmaf(qa[i].z, kb[j].z, s[i][j]);
                    s[i][j] = fmaf(qa[i].w, kb[j].w, s[i][j]);
                }
        }
        bool diag = (mt == rt);
        #pragma unroll
        for (int i = 0; i < 4; i++) {
            float4 sv;
            float* svp = &sv.x;
            #pragma unroll
            for (int j = 0; j < 4; j++) {
                float v = s[i][j];
                v = v / (1.0f + expf(-v)) * invN;
                if (diag && (m0 + c0 + j) > (row0 + r0 + i)) v = 0.0f;
                svp[j] = v;
            }
            *(float4*)&Ss[(r0 + i) * ASTRIDE + c0] = sv;
        }
        __syncthreads();

        #pragma unroll
        for (int m = 0; m < 64; m += 4) {
            float4 sa[4], vb[4];
            #pragma unroll
            for (int i = 0; i < 4; i++) sa[i] = *(const float4*)&Ss[(r0 + i) * ASTRIDE + m];
            #pragma unroll
            for (int t = 0; t < 4; t++) vb[t] = *(const float4*)&Vs[(m + t) * ASTRIDE + c0];
            #pragma unroll
            for (int i = 0; i < 4; i++) {
                float sav[4] = {sa[i].x, sa[i].y, sa[i].z, sa[i].w};
                #pragma unroll
                for (int t = 0; t < 4; t++) {
                    float* vbp = &vb[t].x;
                    #pragma unroll
                    for (int j = 0; j < 4; j++)
                        o[i][j] = fmaf(sav[t], vbp[j], o[i][j]);
                }
            }
        }
        __syncthreads();
    }

    #pragma unroll
    for (int i = 0; i < 4; i++) {
        size_t row = (size_t)b * NN + row0 + r0 + i;
        *(float4*)(attn + row * DD + hc + c0) =
            make_float4(o[i][0], o[i][1], o[i][2], o[i][3]);
    }
}

// ---------------- launch ----------------------------------------------------
extern "C" void kernel_launch(void* const* d_in, const int* in_sizes, int n_in,
                              void* d_out, int out_size)
{
    const float* x    = (const float*)d_in[0];
    // d_in[1] = invalid_attn_mask (causal tril) — implemented analytically
    const float* uvqk = (const float*)d_in[2];
    const float* o_w  = (const float*)d_in[3];
    const float* o_b  = (const float*)d_in[4];
    float* out = (float*)d_out;

    float *p_normed, *p_proj, *p_attn, *p_oin;
    cudaGetSymbolAddress((void**)&p_normed, g_normed);
    cudaGetSymbolAddress((void**)&p_proj,   g_proj);
    cudaGetSymbolAddress((void**)&p_attn,   g_attn);
    cudaGetSymbolAddress((void**)&p_oin,    g_oin);

    // 1. LayerNorm(x)
    ln_kernel<<<TOK, 128>>>(x, p_normed);

    // 2. proj = silu(normed @ uvqk)   [8192 x 2048]
    gemm128<0><<<dim3(EE/128, TOK/128), 256>>>(p_normed, uvqk, p_proj,
                                               TOK, EE, DD, nullptr, nullptr);

    // 3. fused causal HSTU attention
    static bool attr_set = false;
    if (!attr_set) {
        cudaFuncSetAttribute(attn_kernel, cudaFuncAttributeMaxDynamicSharedMemorySize,
                             ATTN_SMEM);
        attr_set = true;
    }
    attn_kernel<<<dim3(NN/64, BB*HH), 256, ATTN_SMEM>>>(p_proj, p_attn);

    // 4. o_in = u * LayerNorm(attn)
    ln_mul_kernel<<<TOK, 128>>>(p_attn, p_proj, p_oin);

    // 5. out = o_in @ o_w^T + o_b + x
    gemm128<1><<<dim3(DD/128, TOK/128), 256>>>(p_oin, o_w, out,
                                               TOK, DD, DD, o_b, x);
}

// round 6
// speedup vs baseline: 1.9709x; 1.9709x over previous
#include <cuda_runtime.h>
#include <cuda_bf16.h>
#include <math.h>
#include <stdint.h>

#define BB 4
#define NN 2048
#define DD 512
#define HH 8
#define EE 2048            // 2*64*8 + 2*64*8
#define TOK (BB*NN)        // 8192

// ---------------- scratch (device globals; no allocation allowed) ----------
__device__ float g_proj  [TOK*EE];            // 67 MB  (u|v|q|k) fp32
__device__ float g_attn  [TOK*DD];            // 16.8 MB
__device__ __nv_bfloat16 g_a_hi [TOK*DD];     // LN(x) hi
__device__ __nv_bfloat16 g_a_lo [TOK*DD];     // LN(x) lo
__device__ __nv_bfloat16 g_bT_hi[EE*DD];      // uvqk^T hi  [2048 x 512] K-major
__device__ __nv_bfloat16 g_bT_lo[EE*DD];
__device__ __nv_bfloat16 g_w_hi [DD*DD];      // o_w hi     [512 x 512] (N,K)
__device__ __nv_bfloat16 g_w_lo [DD*DD];
__device__ __nv_bfloat16 g_oi_hi[TOK*DD];     // o_input hi
__device__ __nv_bfloat16 g_oi_lo[TOK*DD];

__device__ __forceinline__ void split_bf16(float v, __nv_bfloat16& h, __nv_bfloat16& l) {
    h = __float2bfloat16(v);
    l = __float2bfloat16(v - __bfloat162float(h));
}

// ---------------- LayerNorm(x) -> bf16 hi/lo --------------------------------
__global__ __launch_bounds__(128) void ln_split_kernel(const float* __restrict__ x,
                                                       __nv_bfloat16* __restrict__ ahi,
                                                       __nv_bfloat16* __restrict__ alo)
{
    __shared__ float sh1[4], sh2[4];
    int row = blockIdx.x;
    int t = threadIdx.x;
    float4 a = ((const float4*)(x + (size_t)row*DD))[t];
    float s  = a.x + a.y + a.z + a.w;
    float ss = a.x*a.x + a.y*a.y + a.z*a.z + a.w*a.w;
    #pragma unroll
    for (int o = 16; o > 0; o >>= 1) {
        s  += __shfl_down_sync(0xffffffffu, s,  o);
        ss += __shfl_down_sync(0xffffffffu, ss, o);
    }
    int w = t >> 5, l = t & 31;
    if (l == 0) { sh1[w] = s; sh2[w] = ss; }
    __syncthreads();
    s  = sh1[0] + sh1[1] + sh1[2] + sh1[3];
    ss = sh2[0] + sh2[1] + sh2[2] + sh2[3];
    float mu  = s * (1.0f/DD);
    float var = ss * (1.0f/DD) - mu*mu;
    float inv = rsqrtf(var + 1e-6f);
    float v[4] = {(a.x-mu)*inv, (a.y-mu)*inv, (a.z-mu)*inv, (a.w-mu)*inv};
    uint2 ph, pl;
    unsigned short hs[4], ls[4];
    #pragma unroll
    for (int i = 0; i < 4; i++) {
        __nv_bfloat16 h, lo;
        split_bf16(v[i], h, lo);
        hs[i] = __bfloat16_as_ushort(h);
        ls[i] = __bfloat16_as_ushort(lo);
    }
    ph.x = hs[0] | ((uint32_t)hs[1] << 16); ph.y = hs[2] | ((uint32_t)hs[3] << 16);
    pl.x = ls[0] | ((uint32_t)ls[1] << 16); pl.y = ls[2] | ((uint32_t)ls[3] << 16);
    *(uint2*)(ahi + (size_t)row*DD + t*4) = ph;
    *(uint2*)(alo + (size_t)row*DD + t*4) = pl;
}

// ---------------- u * LayerNorm(attn) -> bf16 hi/lo --------------------------
__global__ __launch_bounds__(128) void ln_mul_split_kernel(const float* __restrict__ attn,
                                                           const float* __restrict__ proj,
                                                           __nv_bfloat16* __restrict__ ohi,
                                                           __nv_bfloat16* __restrict__ olo)
{
    __shared__ float sh1[4], sh2[4];
    int row = blockIdx.x;
    int t = threadIdx.x;
    float4 a = ((const float4*)(attn + (size_t)row*DD))[t];
    float s  = a.x + a.y + a.z + a.w;
    float ss = a.x*a.x + a.y*a.y + a.z*a.z + a.w*a.w;
    #pragma unroll
    for (int o = 16; o > 0; o >>= 1) {
        s  += __shfl_down_sync(0xffffffffu, s,  o);
        ss += __shfl_down_sync(0xffffffffu, ss, o);
    }
    int w = t >> 5, l = t & 31;
    if (l == 0) { sh1[w] = s; sh2[w] = ss; }
    __syncthreads();
    s  = sh1[0] + sh1[1] + sh1[2] + sh1[3];
    ss = sh2[0] + sh2[1] + sh2[2] + sh2[3];
    float mu  = s * (1.0f/DD);
    float var = ss * (1.0f/DD) - mu*mu;
    float inv = rsqrtf(var + 1e-6f);
    float4 u = ((const float4*)(proj + (size_t)row*EE))[t];
    float v[4] = {u.x*(a.x-mu)*inv, u.y*(a.y-mu)*inv, u.z*(a.z-mu)*inv, u.w*(a.w-mu)*inv};
    uint2 ph, pl;
    unsigned short hs[4], ls[4];
    #pragma unroll
    for (int i = 0; i < 4; i++) {
        __nv_bfloat16 h, lo;
        split_bf16(v[i], h, lo);
        hs[i] = __bfloat16_as_ushort(h);
        ls[i] = __bfloat16_as_ushort(lo);
    }
    ph.x = hs[0] | ((uint32_t)hs[1] << 16); ph.y = hs[2] | ((uint32_t)hs[3] << 16);
    pl.x = ls[0] | ((uint32_t)ls[1] << 16); pl.y = ls[2] | ((uint32_t)ls[3] << 16);
    *(uint2*)(ohi + (size_t)row*DD + t*4) = ph;
    *(uint2*)(olo + (size_t)row*DD + t*4) = pl;
}

// ---------------- transpose + split uvqk [512,2048] -> [2048,512] ------------
__global__ __launch_bounds__(256) void transpose_split_kernel(const float* __restrict__ in,
                                                              __nv_bfloat16* __restrict__ bhi,
                                                              __nv_bfloat16* __restrict__ blo,
                                                              int n_off)
{
    __shared__ float tile[32][33];
    int n0 = n_off + blockIdx.x * 32;
    int k0 = blockIdx.y * 32;
    int tx = threadIdx.x & 31, ty = threadIdx.x >> 5;   // 32 x 8
    #pragma unroll
    for (int i = 0; i < 4; i++) {
        int k = k0 + ty + i * 8;
        tile[ty + i*8][tx] = in[(size_t)k * EE + n0 + tx];
    }
    __syncthreads();
    #pragma unroll
    for (int i = 0; i < 4; i++) {
        int r = ty + i * 8;                // local n
        float v = tile[tx][r];
        __nv_bfloat16 h, lo;
        split_bf16(v, h, lo);
        size_t idx = (size_t)(n0 + r) * DD + k0 + tx;
        bhi[idx] = h; blo[idx] = lo;
    }
}

// ---------------- split o_w elementwise -------------------------------------
__global__ __launch_bounds__(256) void split_w_kernel(const float* __restrict__ w,
                                                      __nv_bfloat16* __restrict__ whi,
                                                      __nv_bfloat16* __restrict__ wlo)
{
    int i = blockIdx.x * 256 + threadIdx.x;   // DD*DD = 262144
    float v = w[i];
    __nv_bfloat16 h, lo;
    split_bf16(v, h, lo);
    whi[i] = h; wlo[i] = lo;
}

// ============ mma.sync split-bf16 GEMM: C = epi(A @ B^T) =====================
// A hi/lo [M,K] row-major bf16, B hi/lo [N,K] row-major bf16 (K-major).
// CTA tile 128x128, 8 warps = 4(m) x 2(n), warp tile 32x64, K-chunk 32.
// MODE 0: silu;  MODE 1: + bias + resid.
#define GS_ROWB 80                         // 64 B data + 16 B pad per SMEM row
#define GS_TEN  (128 * GS_ROWB)            // 10240 B per tensor tile

__device__ __forceinline__ void mma16816(float* c, const uint32_t* a, const uint32_t* b) {
    asm volatile(
        "mma.sync.aligned.m16n8k16.row.col.f32.bf16.bf16.f32 "
        "{%0,%1,%2,%3}, {%4,%5,%6,%7}, {%8,%9}, {%0,%1,%2,%3};"
        : "+f"(c[0]), "+f"(c[1]), "+f"(c[2]), "+f"(c[3])
        : "r"(a[0]), "r"(a[1]), "r"(a[2]), "r"(a[3]), "r"(b[0]), "r"(b[1]));
}
__device__ __forceinline__ uint32_t lds32(const char* p) { return *(const uint32_t*)p; }

template<int MODE>
__global__ __launch_bounds__(256, 2) void mma_gemm(
    const __nv_bfloat16* __restrict__ Ahi, const __nv_bfloat16* __restrict__ Alo,
    const __nv_bfloat16* __restrict__ Bhi, const __nv_bfloat16* __restrict__ Blo,
    float* __restrict__ C, int K, int ldc,
    const float* __restrict__ bias, const float* __restrict__ resid)
{
    __shared__ char sm[4 * GS_TEN];        // 40960 B: Ahi|Alo|Bhi|Blo
    char* sAh = sm;
    char* sAl = sm + GS_TEN;
    char* sBh = sm + 2 * GS_TEN;
    char* sBl = sm + 3 * GS_TEN;

    int tid = threadIdx.x;
    int lane = tid & 31, wid = tid >> 5;
    int wm = wid & 3, wn = wid >> 2;       // 4 x 2 warp grid
    int m0 = blockIdx.y * 128, n0 = blockIdx.x * 128;

    float acc[2][8][4] = {};

    // per-thread load slot: r = idx>>2 (row 0..127), c = idx&3 (16B chunk)
    for (int k0 = 0; k0 < K; k0 += 32) {
        __syncthreads();
        #pragma unroll
        for (int i = 0; i < 2; i++) {
            int idx = tid + i * 256;
            int r = idx >> 2, c = idx & 3;
            uint32_t so = r * GS_ROWB + c * 16;
            size_t goA = (size_t)(m0 + r) * K + k0 + c * 8;
            size_t goB = (size_t)(n0 + r) * K + k0 + c * 8;
            *(uint4*)(sAh + so) = *(const uint4*)(Ahi + goA);
            *(uint4*)(sAl + so) = *(const uint4*)(Alo + goA);
            *(uint4*)(sBh + so) = *(const uint4*)(Bhi + goB);
            *(uint4*)(sBl + so) = *(const uint4*)(Blo + goB);
        }
        __syncthreads();

        #pragma unroll
        for (int kk = 0; kk < 2; kk++) {
            // A fragments: 2 m16 frags per warp (rows wm*32 + mf*16)
            uint32_t ah[2][4], al[2][4];
            int cb = (kk * 16 + (lane & 3) * 2) * 2;   // byte offset within row
            #pragma unroll
            for (int mf = 0; mf < 2; mf++) {
                int row = wm * 32 + mf * 16 + (lane >> 2);
                const char* pa = sAh + row * GS_ROWB + cb;
                ah[mf][0] = lds32(pa);
                ah[mf][1] = lds32(pa + 8 * GS_ROWB);
                ah[mf][2] = lds32(pa + 16);
                ah[mf][3] = lds32(pa + 8 * GS_ROWB + 16);
                const char* pl = sAl + row * GS_ROWB + cb;
                al[mf][0] = lds32(pl);
                al[mf][1] = lds32(pl + 8 * GS_ROWB);
                al[mf][2] = lds32(pl + 16);
                al[mf][3] = lds32(pl + 8 * GS_ROWB + 16);
            }
            #pragma unroll
            for (int nf = 0; nf < 8; nf++) {
                int n = wn * 64 + nf * 8 + (lane >> 2);
                const char* pb = sBh + n * GS_ROWB + cb;
                uint32_t bh[2] = { lds32(pb), lds32(pb + 16) };
                const char* pbl = sBl + n * GS_ROWB + cb;
                uint32_t bl[2] = { lds32(pbl), lds32(pbl + 16) };
                #pragma unroll
                for (int mf = 0; mf < 2; mf++) {
                    mma16816(acc[mf][nf], ah[mf], bh);
                    mma16816(acc[mf][nf], ah[mf], bl);
                    mma16816(acc[mf][nf], al[mf], bh);
                }
            }
        }
    }

    // epilogue: c0,c1 at (row, col..col+1); c2,c3 at (row+8, ...)
    #pragma unroll
    for (int mf = 0; mf < 2; mf++) {
        int row = m0 + wm * 32 + mf * 16 + (lane >> 2);
        #pragma unroll
        for (int nf = 0; nf < 8; nf++) {
            int col = n0 + wn * 64 + nf * 8 + (lane & 3) * 2;
            float* a4 = acc[mf][nf];
            float v0, v1, v2, v3;
            if (MODE == 0) {
                v0 = a4[0] / (1.0f + expf(-a4[0]));
                v1 = a4[1] / (1.0f + expf(-a4[1]));
                v2 = a4[2] / (1.0f + expf(-a4[2]));
                v3 = a4[3] / (1.0f + expf(-a4[3]));
            } else {
                float b0 = bias[col], b1 = bias[col + 1];
                v0 = a4[0] + b0 + resid[(size_t)row * ldc + col];
                v1 = a4[1] + b1 + resid[(size_t)row * ldc + col + 1];
                v2 = a4[2] + b0 + resid[(size_t)(row + 8) * ldc + col];
                v3 = a4[3] + b1 + resid[(size_t)(row + 8) * ldc + col + 1];
            }
            *(float2*)(C + (size_t)row * ldc + col)       = make_float2(v0, v1);
            *(float2*)(C + (size_t)(row + 8) * ldc + col) = make_float2(v2, v3);
        }
    }
}

// ---------------- fused causal HSTU attention (SIMT fp32) -------------------
#define ASTRIDE 68
#define ATTN_SMEM (4 * 64 * ASTRIDE * (int)sizeof(float))

__global__ __launch_bounds__(256) void attn_kernel(const float* __restrict__ proj,
                                                   float* __restrict__ attn)
{
    extern __shared__ float sm[];
    float* Qs = sm;
    float* Ks = Qs + 64 * ASTRIDE;
    float* Vs = Ks + 64 * ASTRIDE;
    float* Ss = Vs + 64 * ASTRIDE;

    int tid = threadIdx.x;
    int tx = tid & 15, ty = tid >> 4;
    int rt = blockIdx.x;
    int bh = blockIdx.y;
    int b = bh >> 3, h = bh & 7;
    int row0 = rt * 64;
    const size_t base = (size_t)b * NN * EE;
    const int hc = h * 64;

    #pragma unroll
    for (int i = 0; i < 4; i++) {
        int idx = tid + i * 256;
        int r = idx >> 4;
        int d = (idx & 15) * 4;
        float4 q = *(const float4*)(proj + base + (size_t)(row0 + r) * EE + 1024 + hc + d);
        *(float4*)&Qs[r * ASTRIDE + d] = q;
    }

    float o[4][4] = {};
    int r0 = ty * 4, c0 = tx * 4;
    const float invN = 1.0f / (float)NN;

    for (int mt = 0; mt <= rt; mt++) {
        int m0 = mt * 64;
        #pragma unroll
        for (int i = 0; i < 4; i++) {
            int idx = tid + i * 256;
            int r = idx >> 4;
            int d = (idx & 15) * 4;
            float4 kv = *(const float4*)(proj + base + (size_t)(m0 + r) * EE + 1536 + hc + d);
            *(float4*)&Ks[r * ASTRIDE + d] = kv;
            float4 vv = *(const float4*)(proj + base + (size_t)(m0 + r) * EE + 512 + hc + d);
            *(float4*)&Vs[r * ASTRIDE + d] = vv;
        }
        __syncthreads();

        float s[4][4] = {};
        #pragma unroll
        for (int d = 0; d < 64; d += 4) {
            float4 qa[4], kb[4];
            #pragma unroll
            for (int i = 0; i < 4; i++) qa[i] = *(const float4*)&Qs[(r0 + i) * ASTRIDE + d];
            #pragma unroll
            for (int j = 0; j < 4; j++) kb[j] = *(const float4*)&Ks[(c0 + j) * ASTRIDE + d];
            #pragma unroll
            for (int i = 0; i < 4; i++)
                #pragma unroll
                for (int j = 0; j < 4; j++) {
                    s[i][j] = fmaf(qa[i].x, kb[j].x, s[i][j]);
                    s[i][j] = fmaf(qa[i].y, kb[j].y, s[i][j]);
                    s[i][j] = fmaf(qa[i].z, kb[j].z, s[i][j]);
                    s[i][j] = fmaf(qa[i].w, kb[j].w, s[i][j]);
                }
        }
        bool diag = (mt == rt);
        #pragma unroll
        for (int i = 0; i < 4; i++) {
            float4 sv;
            float* svp = &sv.x;
            #pragma unroll
            for (int j = 0; j < 4; j++) {
                float v = s[i][j];
                v = v / (1.0f + expf(-v)) * invN;
                if (diag && (m0 + c0 + j) > (row0 + r0 + i)) v = 0.0f;
                svp[j] = v;
            }
            *(float4*)&Ss[(r0 + i) * ASTRIDE + c0] = sv;
        }
        __syncthreads();

        #pragma unroll
        for (int m = 0; m < 64; m += 4) {
            float4 sa[4], vb[4];
            #pragma unroll
            for (int i = 0; i < 4; i++) sa[i] = *(const float4*)&Ss[(r0 + i) * ASTRIDE + m];
            #pragma unroll
            for (int t = 0; t < 4; t++) vb[t] = *(const float4*)&Vs[(m + t) * ASTRIDE + c0];
            #pragma unroll
            for (int i = 0; i < 4; i++) {
                float sav[4] = {sa[i].x, sa[i].y, sa[i].z, sa[i].w};
                #pragma unroll
                for (int t = 0; t < 4; t++) {
                    float* vbp = &vb[t].x;
                    #pragma unroll
                    for (int j = 0; j < 4; j++)
                        o[i][j] = fmaf(sav[t], vbp[j], o[i][j]);
                }
            }
        }
        __syncthreads();
    }

    #pragma unroll
    for (int i = 0; i < 4; i++) {
        size_t row = (size_t)b * NN + row0 + r0 + i;
        *(float4*)(attn + row * DD + hc + c0) =
            make_float4(o[i][0], o[i][1], o[i][2], o[i][3]);
    }
}

// ---------------- launch ----------------------------------------------------
extern "C" void kernel_launch(void* const* d_in, const int* in_sizes, int n_in,
                              void* d_out, int out_size)
{
    const float* x    = (const float*)d_in[0];
    // d_in[1] = invalid_attn_mask (causal tril) — implemented analytically
    const float* uvqk = (const float*)d_in[2];
    const float* o_w  = (const float*)d_in[3];
    const float* o_b  = (const float*)d_in[4];
    float* out = (float*)d_out;

    float *p_proj, *p_attn;
    __nv_bfloat16 *p_ahi, *p_alo, *p_bhi, *p_blo, *p_whi, *p_wlo, *p_ohi, *p_olo;
    cudaGetSymbolAddress((void**)&p_proj, g_proj);
    cudaGetSymbolAddress((void**)&p_attn, g_attn);
    cudaGetSymbolAddress((void**)&p_ahi,  g_a_hi);
    cudaGetSymbolAddress((void**)&p_alo,  g_a_lo);
    cudaGetSymbolAddress((void**)&p_bhi,  g_bT_hi);
    cudaGetSymbolAddress((void**)&p_blo,  g_bT_lo);
    cudaGetSymbolAddress((void**)&p_whi,  g_w_hi);
    cudaGetSymbolAddress((void**)&p_wlo,  g_w_lo);
    cudaGetSymbolAddress((void**)&p_ohi,  g_oi_hi);
    cudaGetSymbolAddress((void**)&p_olo,  g_oi_lo);

    static bool attr_set = false;
    if (!attr_set) {
        cudaFuncSetAttribute(attn_kernel, cudaFuncAttributeMaxDynamicSharedMemorySize,
                             ATTN_SMEM);
        attr_set = true;
    }

    // 1. LayerNorm(x) -> bf16 hi/lo
    ln_split_kernel<<<TOK, 128>>>(x, p_ahi, p_alo);
    // 2-3. transpose+split uvqk
    transpose_split_kernel<<<dim3(32, 16), 256>>>(uvqk, p_bhi, p_blo, 0);
    transpose_split_kernel<<<dim3(32, 16), 256>>>(uvqk, p_bhi, p_blo, 1024);
    // 4. split o_w
    split_w_kernel<<<DD*DD/256, 256>>>(o_w, p_whi, p_wlo);
    // 5. proj = silu(normed @ uvqk) via mma.sync
    mma_gemm<0><<<dim3(EE/128, TOK/128), 256>>>(
        p_ahi, p_alo, p_bhi, p_blo, p_proj, DD, EE, nullptr, nullptr);
    // 6. fused causal HSTU attention (launch #6 -> captured by ncu -s 5 -c 1)
    attn_kernel<<<dim3(NN/64, BB*HH), 256, ATTN_SMEM>>>(p_proj, p_attn);
    // 7. o_in = u * LayerNorm(attn) -> bf16 hi/lo
    ln_mul_split_kernel<<<TOK, 128>>>(p_attn, p_proj, p_ohi, p_olo);
    // 8. out = o_in @ o_w^T + o_b + x via mma.sync
    mma_gemm<1><<<dim3(DD/128, TOK/128), 256>>>(
        p_ohi, p_olo, p_whi, p_wlo, out, DD, DD, o_b, x);
}

// round 11
// speedup vs baseline: 3.7493x; 1.9023x over previous
#include <cuda_runtime.h>
#include <cuda_bf16.h>
#include <math.h>
#include <stdint.h>

#define BB 4
#define NN 2048
#define DD 512
#define HH 8
#define EE 2048            // 2*64*8 + 2*64*8
#define TOK (BB*NN)        // 8192

// ---------------- scratch (device globals; no allocation allowed) ----------
__device__ float g_proj  [TOK*EE];            // 67 MB  (u|v|q|k) fp32
__device__ float g_attn  [TOK*DD];            // 16.8 MB
__device__ __nv_bfloat16 g_a_hi [TOK*DD];     // LN(x) hi
__device__ __nv_bfloat16 g_a_lo [TOK*DD];     // LN(x) lo
__device__ __nv_bfloat16 g_bT_hi[EE*DD];      // uvqk^T hi  [2048 x 512] K-major
__device__ __nv_bfloat16 g_bT_lo[EE*DD];
__device__ __nv_bfloat16 g_w_hi [DD*DD];      // o_w hi     [512 x 512] (N,K)
__device__ __nv_bfloat16 g_w_lo [DD*DD];
__device__ __nv_bfloat16 g_oi_hi[TOK*DD];     // o_input hi
__device__ __nv_bfloat16 g_oi_lo[TOK*DD];

__device__ __forceinline__ void split_bf16(float v, __nv_bfloat16& h, __nv_bfloat16& l) {
    h = __float2bfloat16(v);
    l = __float2bfloat16(v - __bfloat162float(h));
}
__device__ __forceinline__ uint32_t pack2(__nv_bfloat16 a, __nv_bfloat16 b) {
    return (uint32_t)__bfloat16_as_ushort(a) | ((uint32_t)__bfloat16_as_ushort(b) << 16);
}

// ---------------- LayerNorm(x) -> bf16 hi/lo --------------------------------
__global__ __launch_bounds__(128) void ln_split_kernel(const float* __restrict__ x,
                                                       __nv_bfloat16* __restrict__ ahi,
                                                       __nv_bfloat16* __restrict__ alo)
{
    __shared__ float sh1[4], sh2[4];
    int row = blockIdx.x;
    int t = threadIdx.x;
    float4 a = ((const float4*)(x + (size_t)row*DD))[t];
    float s  = a.x + a.y + a.z + a.w;
    float ss = a.x*a.x + a.y*a.y + a.z*a.z + a.w*a.w;
    #pragma unroll
    for (int o = 16; o > 0; o >>= 1) {
        s  += __shfl_down_sync(0xffffffffu, s,  o);
        ss += __shfl_down_sync(0xffffffffu, ss, o);
    }
    int w = t >> 5, l = t & 31;
    if (l == 0) { sh1[w] = s; sh2[w] = ss; }
    __syncthreads();
    s  = sh1[0] + sh1[1] + sh1[2] + sh1[3];
    ss = sh2[0] + sh2[1] + sh2[2] + sh2[3];
    float mu  = s * (1.0f/DD);
    float var = ss * (1.0f/DD) - mu*mu;
    float inv = rsqrtf(var + 1e-6f);
    float v[4] = {(a.x-mu)*inv, (a.y-mu)*inv, (a.z-mu)*inv, (a.w-mu)*inv};
    uint2 ph, pl;
    __nv_bfloat16 h0,l0,h1,l1,h2,l2,h3,l3;
    split_bf16(v[0],h0,l0); split_bf16(v[1],h1,l1);
    split_bf16(v[2],h2,l2); split_bf16(v[3],h3,l3);
    ph.x = pack2(h0,h1); ph.y = pack2(h2,h3);
    pl.x = pack2(l0,l1); pl.y = pack2(l2,l3);
    *(uint2*)(ahi + (size_t)row*DD + t*4) = ph;
    *(uint2*)(alo + (size_t)row*DD + t*4) = pl;
}

// ---------------- u * LayerNorm(attn) -> bf16 hi/lo --------------------------
__global__ __launch_bounds__(128) void ln_mul_split_kernel(const float* __restrict__ attn,
                                                           const float* __restrict__ proj,
                                                           __nv_bfloat16* __restrict__ ohi,
                                                           __nv_bfloat16* __restrict__ olo)
{
    __shared__ float sh1[4], sh2[4];
    int row = blockIdx.x;
    int t = threadIdx.x;
    float4 a = ((const float4*)(attn + (size_t)row*DD))[t];
    float s  = a.x + a.y + a.z + a.w;
    float ss = a.x*a.x + a.y*a.y + a.z*a.z + a.w*a.w;
    #pragma unroll
    for (int o = 16; o > 0; o >>= 1) {
        s  += __shfl_down_sync(0xffffffffu, s,  o);
        ss += __shfl_down_sync(0xffffffffu, ss, o);
    }
    int w = t >> 5, l = t & 31;
    if (l == 0) { sh1[w] = s; sh2[w] = ss; }
    __syncthreads();
    s  = sh1[0] + sh1[1] + sh1[2] + sh1[3];
    ss = sh2[0] + sh2[1] + sh2[2] + sh2[3];
    float mu  = s * (1.0f/DD);
    float var = ss * (1.0f/DD) - mu*mu;
    float inv = rsqrtf(var + 1e-6f);
    float4 u = ((const float4*)(proj + (size_t)row*EE))[t];
    float v[4] = {u.x*(a.x-mu)*inv, u.y*(a.y-mu)*inv, u.z*(a.z-mu)*inv, u.w*(a.w-mu)*inv};
    uint2 ph, pl;
    __nv_bfloat16 h0,l0,h1,l1,h2,l2,h3,l3;
    split_bf16(v[0],h0,l0); split_bf16(v[1],h1,l1);
    split_bf16(v[2],h2,l2); split_bf16(v[3],h3,l3);
    ph.x = pack2(h0,h1); ph.y = pack2(h2,h3);
    pl.x = pack2(l0,l1); pl.y = pack2(l2,l3);
    *(uint2*)(ohi + (size_t)row*DD + t*4) = ph;
    *(uint2*)(olo + (size_t)row*DD + t*4) = pl;
}

// ---------------- transpose + split uvqk [512,2048] -> [2048,512] ------------
__global__ __launch_bounds__(256) void transpose_split_kernel(const float* __restrict__ in,
                                                              __nv_bfloat16* __restrict__ bhi,
                                                              __nv_bfloat16* __restrict__ blo)
{
    __shared__ float tile[32][33];
    int n0 = blockIdx.x * 32;              // 0..2047
    int k0 = blockIdx.y * 32;
    int tx = threadIdx.x & 31, ty = threadIdx.x >> 5;   // 32 x 8
    #pragma unroll
    for (int i = 0; i < 4; i++) {
        int k = k0 + ty + i * 8;
        tile[ty + i*8][tx] = in[(size_t)k * EE + n0 + tx];
    }
    __syncthreads();
    #pragma unroll
    for (int i = 0; i < 4; i++) {
        int r = ty + i * 8;                // local n
        float v = tile[tx][r];
        __nv_bfloat16 h, lo;
        split_bf16(v, h, lo);
        size_t idx = (size_t)(n0 + r) * DD + k0 + tx;
        bhi[idx] = h; blo[idx] = lo;
    }
}

// ---------------- split o_w elementwise -------------------------------------
__global__ __launch_bounds__(256) void split_w_kernel(const float* __restrict__ w,
                                                      __nv_bfloat16* __restrict__ whi,
                                                      __nv_bfloat16* __restrict__ wlo)
{
    int i = blockIdx.x * 256 + threadIdx.x;   // DD*DD = 262144
    float v = w[i];
    __nv_bfloat16 h, lo;
    split_bf16(v, h, lo);
    whi[i] = h; wlo[i] = lo;
}

// ============ mma.sync split-bf16 GEMM: C = epi(A @ B^T) =====================
#define GS_ROWB 80                         // 64 B data + 16 B pad per SMEM row
#define GS_TEN  (128 * GS_ROWB)            // 10240 B per tensor tile

__device__ __forceinline__ void mma16816(float* c, const uint32_t* a, const uint32_t* b) {
    asm volatile(
        "mma.sync.aligned.m16n8k16.row.col.f32.bf16.bf16.f32 "
        "{%0,%1,%2,%3}, {%4,%5,%6,%7}, {%8,%9}, {%0,%1,%2,%3};"
        : "+f"(c[0]), "+f"(c[1]), "+f"(c[2]), "+f"(c[3])
        : "r"(a[0]), "r"(a[1]), "r"(a[2]), "r"(a[3]), "r"(b[0]), "r"(b[1]));
}
__device__ __forceinline__ uint32_t lds32(const char* p) { return *(const uint32_t*)p; }

template<int MODE>
__global__ __launch_bounds__(256, 2) void mma_gemm(
    const __nv_bfloat16* __restrict__ Ahi, const __nv_bfloat16* __restrict__ Alo,
    const __nv_bfloat16* __restrict__ Bhi, const __nv_bfloat16* __restrict__ Blo,
    float* __restrict__ C, int K, int ldc,
    const float* __restrict__ bias, const float* __restrict__ resid)
{
    __shared__ char sm[4 * GS_TEN];        // 40960 B: Ahi|Alo|Bhi|Blo
    char* sAh = sm;
    char* sAl = sm + GS_TEN;
    char* sBh = sm + 2 * GS_TEN;
    char* sBl = sm + 3 * GS_TEN;

    int tid = threadIdx.x;
    int lane = tid & 31, wid = tid >> 5;
    int wm = wid & 3, wn = wid >> 2;       // 4 x 2 warp grid
    int m0 = blockIdx.y * 128, n0 = blockIdx.x * 128;

    float acc[2][8][4] = {};

    for (int k0 = 0; k0 < K; k0 += 32) {
        __syncthreads();
        #pragma unroll
        for (int i = 0; i < 2; i++) {
            int idx = tid + i * 256;
            int r = idx >> 2, c = idx & 3;
            uint32_t so = r * GS_ROWB + c * 16;
            size_t goA = (size_t)(m0 + r) * K + k0 + c * 8;
            size_t goB = (size_t)(n0 + r) * K + k0 + c * 8;
            *(uint4*)(sAh + so) = *(const uint4*)(Ahi + goA);
            *(uint4*)(sAl + so) = *(const uint4*)(Alo + goA);
            *(uint4*)(sBh + so) = *(const uint4*)(Bhi + goB);
            *(uint4*)(sBl + so) = *(const uint4*)(Blo + goB);
        }
        __syncthreads();

        #pragma unroll
        for (int kk = 0; kk < 2; kk++) {
            uint32_t ah[2][4], al[2][4];
            int cb = (kk * 16 + (lane & 3) * 2) * 2;
            #pragma unroll
            for (int mf = 0; mf < 2; mf++) {
                int row = wm * 32 + mf * 16 + (lane >> 2);
                const char* pa = sAh + row * GS_ROWB + cb;
                ah[mf][0] = lds32(pa);
                ah[mf][1] = lds32(pa + 8 * GS_ROWB);
                ah[mf][2] = lds32(pa + 16);
                ah[mf][3] = lds32(pa + 8 * GS_ROWB + 16);
                const char* pl = sAl + row * GS_ROWB + cb;
                al[mf][0] = lds32(pl);
                al[mf][1] = lds32(pl + 8 * GS_ROWB);
                al[mf][2] = lds32(pl + 16);
                al[mf][3] = lds32(pl + 8 * GS_ROWB + 16);
            }
            #pragma unroll
            for (int nf = 0; nf < 8; nf++) {
                int n = wn * 64 + nf * 8 + (lane >> 2);
                const char* pb = sBh + n * GS_ROWB + cb;
                uint32_t bh[2] = { lds32(pb), lds32(pb + 16) };
                const char* pbl = sBl + n * GS_ROWB + cb;
                uint32_t bl[2] = { lds32(pbl), lds32(pbl + 16) };
                #pragma unroll
                for (int mf = 0; mf < 2; mf++) {
                    mma16816(acc[mf][nf], ah[mf], bh);
                    mma16816(acc[mf][nf], ah[mf], bl);
                    mma16816(acc[mf][nf], al[mf], bh);
                }
            }
        }
    }

    #pragma unroll
    for (int mf = 0; mf < 2; mf++) {
        int row = m0 + wm * 32 + mf * 16 + (lane >> 2);
        #pragma unroll
        for (int nf = 0; nf < 8; nf++) {
            int col = n0 + wn * 64 + nf * 8 + (lane & 3) * 2;
            float* a4 = acc[mf][nf];
            float v0, v1, v2, v3;
            if (MODE == 0) {
                v0 = a4[0] / (1.0f + expf(-a4[0]));
                v1 = a4[1] / (1.0f + expf(-a4[1]));
                v2 = a4[2] / (1.0f + expf(-a4[2]));
                v3 = a4[3] / (1.0f + expf(-a4[3]));
            } else {
                float b0 = bias[col], b1 = bias[col + 1];
                v0 = a4[0] + b0 + resid[(size_t)row * ldc + col];
                v1 = a4[1] + b1 + resid[(size_t)row * ldc + col + 1];
                v2 = a4[2] + b0 + resid[(size_t)(row + 8) * ldc + col];
                v3 = a4[3] + b1 + resid[(size_t)(row + 8) * ldc + col + 1];
            }
            *(float2*)(C + (size_t)row * ldc + col)       = make_float2(v0, v1);
            *(float2*)(C + (size_t)(row + 8) * ldc + col) = make_float2(v2, v3);
        }
    }
}

// ============ mma.sync split-bf16 causal HSTU attention ======================
// grid (NN/64, B*H), block 256 (8 warps = 4m x 2n). q-tile 64, key-tile 64.
// SMEM rows stride 144 B -> fragment LDS conflict-free ((4r+t) mod 32 full).
#define AT_ROWB 144
#define AT_TILEB (64 * AT_ROWB)            // 9216 B
#define ATTN_SMEM (8 * AT_TILEB)           // 73728 B

__global__ __launch_bounds__(256, 2) void attn_mma_kernel(const float* __restrict__ proj,
                                                          float* __restrict__ attn)
{
    extern __shared__ char smb[];
    char* Qh  = smb;
    char* Ql  = smb + 1 * AT_TILEB;
    char* Kh  = smb + 2 * AT_TILEB;
    char* Kl  = smb + 3 * AT_TILEB;
    char* Vth = smb + 4 * AT_TILEB;
    char* Vtl = smb + 5 * AT_TILEB;
    char* Sh  = smb + 6 * AT_TILEB;
    char* Sl  = smb + 7 * AT_TILEB;

    int tid = threadIdx.x;
    int lane = tid & 31, wid = tid >> 5;
    int wm = wid & 3, wn = wid >> 2;
    int rt = blockIdx.x, bh = blockIdx.y;
    int b = bh >> 3, h = bh & 7;
    int row0 = rt * 64;
    const size_t base = (size_t)b * NN * EE + h * 64;

    int lr = tid >> 2;            // row 0..63 this thread loads
    int lc = (tid & 3) * 16;      // 16-element d/m chunk

    // ---- load Q once, split, STS ----
    {
        const float* gq = proj + base + (size_t)(row0 + lr) * EE + 1024 + lc;
        float f[16];
        #pragma unroll
        for (int i = 0; i < 4; i++) {
            float4 t4 = *(const float4*)(gq + i * 4);
            f[i*4]=t4.x; f[i*4+1]=t4.y; f[i*4+2]=t4.z; f[i*4+3]=t4.w;
        }
        #pragma unroll
        for (int i = 0; i < 8; i++) {
            __nv_bfloat16 h0,l0,h1,l1;
            split_bf16(f[2*i], h0, l0); split_bf16(f[2*i+1], h1, l1);
            uint32_t boff = lr * AT_ROWB + (lc + 2*i) * 2;
            *(uint32_t*)(Qh + boff) = pack2(h0, h1);
            *(uint32_t*)(Ql + boff) = pack2(l0, l1);
        }
    }

    float oacc[4][4] = {};
    const float invN = 1.0f / (float)NN;
    int r_l = wm * 16 + (lane >> 2);          // local q row for fragments

    for (int mt = 0; mt <= rt; mt++) {
        int m0 = mt * 64;
        // prefetch K,V into regs (overlaps prev SV mma)
        float fk[16], fv[16];
        {
            const float* gk = proj + base + (size_t)(m0 + lr) * EE + 1536 + lc;
            const float* gv = proj + base + (size_t)(m0 + lr) * EE + 512  + lc;
            #pragma unroll
            for (int i = 0; i < 4; i++) {
                float4 t4 = *(const float4*)(gk + i * 4);
                fk[i*4]=t4.x; fk[i*4+1]=t4.y; fk[i*4+2]=t4.z; fk[i*4+3]=t4.w;
                float4 v4 = *(const float4*)(gv + i * 4);
                fv[i*4]=v4.x; fv[i*4+1]=v4.y; fv[i*4+2]=v4.z; fv[i*4+3]=v4.w;
            }
        }
        __syncthreads();   // prev iteration's SV done; Q ready on first iter
        // STS K (packed pairs)
        #pragma unroll
        for (int i = 0; i < 8; i++) {
            __nv_bfloat16 h0,l0,h1,l1;
            split_bf16(fk[2*i], h0, l0); split_bf16(fk[2*i+1], h1, l1);
            uint32_t boff = lr * AT_ROWB + (lc + 2*i) * 2;
            *(uint32_t*)(Kh + boff) = pack2(h0, h1);
            *(uint32_t*)(Kl + boff) = pack2(l0, l1);
        }
        // STS V transposed: Vt[d][m]
        #pragma unroll
        for (int i = 0; i < 16; i++) {
            __nv_bfloat16 h0, l0;
            split_bf16(fv[i], h0, l0);
            uint32_t boff = (lc + i) * AT_ROWB + lr * 2;
            *(unsigned short*)(Vth + boff) = __bfloat16_as_ushort(h0);
            *(unsigned short*)(Vtl + boff) = __bfloat16_as_ushort(l0);
        }
        __syncthreads();   // K,V tiles ready

        // ---- S = Q K^T ----
        float s[4][4] = {};
        #pragma unroll
        for (int kk = 0; kk < 4; kk++) {
            int cb = (kk * 16 + (lane & 3) * 2) * 2;
            const char* pa = Qh + r_l * AT_ROWB + cb;
            uint32_t ah[4] = { lds32(pa), lds32(pa + 8*AT_ROWB),
                               lds32(pa + 16), lds32(pa + 8*AT_ROWB + 16) };
            const char* pal = Ql + r_l * AT_ROWB + cb;
            uint32_t al[4] = { lds32(pal), lds32(pal + 8*AT_ROWB),
                               lds32(pal + 16), lds32(pal + 8*AT_ROWB + 16) };
            #pragma unroll
            for (int nf = 0; nf < 4; nf++) {
                int n = wn * 32 + nf * 8 + (lane >> 2);
                const char* pb = Kh + n * AT_ROWB + cb;
                uint32_t bh2[2] = { lds32(pb), lds32(pb + 16) };
                const char* pbl = Kl + n * AT_ROWB + cb;
                uint32_t bl2[2] = { lds32(pbl), lds32(pbl + 16) };
                mma16816(s[nf], ah, bh2);
                mma16816(s[nf], ah, bl2);
                mma16816(s[nf], al, bh2);
            }
        }

        // ---- silu/N + causal mask + split -> S SMEM ----
        bool diag = (mt == rt);
        #pragma unroll
        for (int nf = 0; nf < 4; nf++) {
            int c_l = wn * 32 + nf * 8 + (lane & 3) * 2;
            float v[4];
            #pragma unroll
            for (int e = 0; e < 4; e++) {
                float x = s[nf][e];
                v[e] = x / (1.0f + expf(-x)) * invN;
            }
            if (diag) {
                int qr0 = row0 + r_l, qr1 = qr0 + 8;
                int kc0 = m0 + c_l,  kc1 = kc0 + 1;
                if (kc0 > qr0) v[0] = 0.0f;
                if (kc1 > qr0) v[1] = 0.0f;
                if (kc0 > qr1) v[2] = 0.0f;
                if (kc1 > qr1) v[3] = 0.0f;
            }
            __nv_bfloat16 h0,l0,h1,l1;
            split_bf16(v[0], h0, l0); split_bf16(v[1], h1, l1);
            uint32_t b0 = r_l * AT_ROWB + c_l * 2;
            *(uint32_t*)(Sh + b0) = pack2(h0, h1);
            *(uint32_t*)(Sl + b0) = pack2(l0, l1);
            split_bf16(v[2], h0, l0); split_bf16(v[3], h1, l1);
            uint32_t b1 = (r_l + 8) * AT_ROWB + c_l * 2;
            *(uint32_t*)(Sh + b1) = pack2(h0, h1);
            *(uint32_t*)(Sl + b1) = pack2(l0, l1);
        }
        __syncthreads();   // S ready

        // ---- O += S V ----
        #pragma unroll
        for (int kk = 0; kk < 4; kk++) {
            int cb = (kk * 16 + (lane & 3) * 2) * 2;
            const char* pa = Sh + r_l * AT_ROWB + cb;
            uint32_t ah[4] = { lds32(pa), lds32(pa + 8*AT_ROWB),
                               lds32(pa + 16), lds32(pa + 8*AT_ROWB + 16) };
            const char* pal = Sl + r_l * AT_ROWB + cb;
            uint32_t al[4] = { lds32(pal), lds32(pal + 8*AT_ROWB),
                               lds32(pal + 16), lds32(pal + 8*AT_ROWB + 16) };
            #pragma unroll
            for (int nf = 0; nf < 4; nf++) {
                int n = wn * 32 + nf * 8 + (lane >> 2);
                const char* pb = Vth + n * AT_ROWB + cb;
                uint32_t bh2[2] = { lds32(pb), lds32(pb + 16) };
                const char* pbl = Vtl + n * AT_ROWB + cb;
                uint32_t bl2[2] = { lds32(pbl), lds32(pbl + 16) };
                mma16816(oacc[nf], ah, bh2);
                mma16816(oacc[nf], ah, bl2);
                mma16816(oacc[nf], al, bh2);
            }
        }
    }

    // ---- write O ----
    #pragma unroll
    for (int nf = 0; nf < 4; nf++) {
        int dcol = wn * 32 + nf * 8 + (lane & 3) * 2;
        size_t row = (size_t)b * NN + row0 + r_l;
        *(float2*)(attn + row * DD + h * 64 + dcol) =
            make_float2(oacc[nf][0], oacc[nf][1]);
        *(float2*)(attn + (row + 8) * DD + h * 64 + dcol) =
            make_float2(oacc[nf][2], oacc[nf][3]);
    }
}

// ---------------- launch ----------------------------------------------------
extern "C" void kernel_launch(void* const* d_in, const int* in_sizes, int n_in,
                              void* d_out, int out_size)
{
    const float* x    = (const float*)d_in[0];
    // d_in[1] = invalid_attn_mask (causal tril) — implemented analytically
    const float* uvqk = (const float*)d_in[2];
    const float* o_w  = (const float*)d_in[3];
    const float* o_b  = (const float*)d_in[4];
    float* out = (float*)d_out;

    float *p_proj, *p_attn;
    __nv_bfloat16 *p_ahi, *p_alo, *p_bhi, *p_blo, *p_whi, *p_wlo, *p_ohi, *p_olo;
    cudaGetSymbolAddress((void**)&p_proj, g_proj);
    cudaGetSymbolAddress((void**)&p_attn, g_attn);
    cudaGetSymbolAddress((void**)&p_ahi,  g_a_hi);
    cudaGetSymbolAddress((void**)&p_alo,  g_a_lo);
    cudaGetSymbolAddress((void**)&p_bhi,  g_bT_hi);
    cudaGetSymbolAddress((void**)&p_blo,  g_bT_lo);
    cudaGetSymbolAddress((void**)&p_whi,  g_w_hi);
    cudaGetSymbolAddress((void**)&p_wlo,  g_w_lo);
    cudaGetSymbolAddress((void**)&p_ohi,  g_oi_hi);
    cudaGetSymbolAddress((void**)&p_olo,  g_oi_lo);

    static bool attr_set = false;
    if (!attr_set) {
        cudaFuncSetAttribute(attn_mma_kernel,
                             cudaFuncAttributeMaxDynamicSharedMemorySize, ATTN_SMEM);
        attr_set = true;
    }

    // 1. LayerNorm(x) -> bf16 hi/lo
    ln_split_kernel<<<TOK, 128>>>(x, p_ahi, p_alo);
    // 2. transpose+split uvqk (single launch)
    transpose_split_kernel<<<dim3(64, 16), 256>>>(uvqk, p_bhi, p_blo);
    // 3. split o_w
    split_w_kernel<<<DD*DD/256, 256>>>(o_w, p_whi, p_wlo);
    // 4. proj = silu(normed @ uvqk) via mma.sync  (ncu capture slot)
    mma_gemm<0><<<dim3(EE/128, TOK/128), 256>>>(
        p_ahi, p_alo, p_bhi, p_blo, p_proj, DD, EE, nullptr, nullptr);
    // 5. fused causal HSTU attention via mma.sync
    attn_mma_kernel<<<dim3(NN/64, BB*HH), 256, ATTN_SMEM>>>(p_proj, p_attn);
    // 6. o_in = u * LayerNorm(attn) -> bf16 hi/lo
    ln_mul_split_kernel<<<TOK, 128>>>(p_attn, p_proj, p_ohi, p_olo);
    // 7. out = o_in @ o_w^T + o_b + x via mma.sync
    mma_gemm<1><<<dim3(DD/128, TOK/128), 256>>>(
        p_ohi, p_olo, p_whi, p_wlo, out, DD, DD, o_b, x);
}